// round 13
// baseline (speedup 1.0000x reference)
#include <cuda_runtime.h>
#include <cstdint>

// Problem constants
#define BATCH   512
#define OUTF    1024
#define KDIM    128      // NUM_BLOCKS * LATTICE_DIM
#define NIDX    256      // MAX_INDICES

// Tiling for main kernel
#define NSEG    8        // k-segments (grid.y)
#define KSEG    16       // k per segment
#define KCH     2        // k per staging chunk (per buffer)
#define NCH     (KSEG / KCH)       // 8 chunks
#define BT      32       // b per CTA
#define MTHREADS 1024    // 32 warps: warp w owns o = w*32 .. w*32+31
#define BUF_F   (KCH * 32 * 256)   // floats per buffer = 16384 (64 KB)
#define JT_U32  (32 * 4 * 32)      // j-table: [warp][q][lane] u32 = 16 KB

// Per-segment partials, [seg][o][b] (b contiguous): 16 MB
__device__ float g_part[NSEG][OUTF][BATCH];

// ---------------- main kernel: double-buffered conflict-free smem gather ----------------
// CTA (btile, seg): b in [btile*32,+32), k in [seg*16,+16), all 1024 o.
// smem buffers: S[buf][kk][b][ j ^ b ]; gather with lane==b is bank-conflict-free.
// Index distribution: per-warp j-table in smem, read via LDS.128 same-address
// broadcast (1 crossbar slot per 4 o's of indices) instead of per-o SHFL.
__global__ __launch_bounds__(MTHREADS, 1) void lut_main(
    const int*   __restrict__ inp,   // [BATCH, KDIM] int32
    const int*   __restrict__ wgt,   // [OUTF, KDIM]  int32
    const float* __restrict__ lut)   // [256, 256]
{
    extern __shared__ unsigned SM_U[];            // 144 KB total
    unsigned* jt = SM_U;                          // [warp][q][lane] u32
    float*    S  = (float*)(SM_U + JT_U32);       // 2 * BUF_F floats

    const int btile = blockIdx.x;    // 0..15
    const int seg   = blockIdx.y;    // 0..7
    const int tid   = threadIdx.x;
    const int wid   = tid >> 5;
    const int lane  = tid & 31;
    const int obase = wid * 32;

    // ---- fused pack: this lane's 16 weight indices (o = obase+lane) -> j-table ----
    {
        const int* wp = wgt + (obase + lane) * KDIM + seg * KSEG;
        #pragma unroll
        for (int q = 0; q < 4; ++q) {
            int4 v = ((const int4*)wp)[q];
            unsigned jw =
                  (unsigned)min(max(v.x, 0), NIDX - 1)
                | ((unsigned)min(max(v.y, 0), NIDX - 1) << 8)
                | ((unsigned)min(max(v.z, 0), NIDX - 1) << 16)
                | ((unsigned)min(max(v.w, 0), NIDX - 1) << 24);
            jt[(wid * 4 + q) * 32 + lane] = jw;   // bank = lane: conflict-free
        }
    }
    const unsigned lx = (unsigned)lane * 0x0101u;   // xor lane into bytes 0,1

    // ---- staging assignment: warp stages 2 rows (kk fixed, b0 and b0+1) per chunk ----
    const int kw = wid >> 4;              // kk within chunk: 0 or 1
    const int b0 = (wid & 15) * 2;
    const int b1 = b0 + 1;
    const int* ip0 = inp + (btile * BT + b0) * KDIM + seg * KSEG + kw;
    const int* ip1 = inp + (btile * BT + b1) * KDIM + seg * KSEG + kw;
    float* drow0base = S + (kw * 32 + b0) * 256;   // + buf*BUF_F at use
    float* drow1base = S + (kw * 32 + b1) * 256;

    float acc[32];
    #pragma unroll
    for (int i = 0; i < 32; ++i) acc[i] = 0.f;

    // ---- prologue: stage chunk 0 into buffer 0 (LDG.128, scalar swizzled STS) ----
    {
        int r0 = min(max(ip0[0], 0), NIDX - 1);
        int r1 = min(max(ip1[0], 0), NIDX - 1);
        const float4* s0 = (const float4*)(lut + r0 * 256);
        const float4* s1 = (const float4*)(lut + r1 * 256);
        #pragma unroll
        for (int h = 0; h < 2; ++h) {
            float4 a = s0[h * 32 + lane];
            float4 b = s1[h * 32 + lane];
            int j = (h * 32 + lane) * 4;
            drow0base[(j + 0) ^ b0] = a.x; drow0base[(j + 1) ^ b0] = a.y;
            drow0base[(j + 2) ^ b0] = a.z; drow0base[(j + 3) ^ b0] = a.w;
            drow1base[(j + 0) ^ b1] = b.x; drow1base[(j + 1) ^ b1] = b.y;
            drow1base[(j + 2) ^ b1] = b.z; drow1base[(j + 3) ^ b1] = b.w;
        }
    }
    __syncthreads();

    // ---- fully unrolled pipelined chunks (c compile-time: parity/quad fold) ----
    #pragma unroll
    for (int c = 0; c < NCH; ++c) {
        const bool more = (c < NCH - 1);
        const int  qidx = c >> 1;        // which jt word quad
        const int  half = c & 1;         // low/high 16 bits of jt word

        const float4* sA = (const float4*)lut;
        const float4* sB = (const float4*)lut;
        if (more) {
            int r0 = min(max(ip0[(c + 1) * KCH], 0), NIDX - 1);
            int r1 = min(max(ip1[(c + 1) * KCH], 0), NIDX - 1);
            sA = (const float4*)(lut + r0 * 256);
            sB = (const float4*)(lut + r1 * 256);
        }

        const float* Sb = S + (c & 1) * BUF_F + lane * 256;
        const uint4* jql = (const uint4*)(jt + (wid * 4 + qidx) * 32);

        float4 rA0, rA1;
        if (more) { rA0 = sA[lane]; rA1 = sA[32 + lane]; }   // LDG row A

        // gather oo = 0..15 (indices via LDS.128 broadcast)
        #pragma unroll
        for (int g = 0; g < 4; ++g) {
            uint4 qv = jql[g];                     // words for oo = 4g..4g+3
            unsigned u[4] = {qv.x, qv.y, qv.z, qv.w};
            #pragma unroll
            for (int i = 0; i < 4; ++i) {
                unsigned w = (half ? (u[i] >> 16) : (u[i] & 0xFFFFu)) ^ lx;
                acc[4 * g + i] += Sb[w & 255u];
                acc[4 * g + i] += Sb[8192 + (w >> 8)];
            }
        }

        if (more) {
            // STS row A, then LDG row B into the same registers
            float* dA = drow0base + ((c + 1) & 1) * BUF_F;
            int j0 = lane * 4, j1 = (32 + lane) * 4;
            dA[(j0 + 0) ^ b0] = rA0.x; dA[(j0 + 1) ^ b0] = rA0.y;
            dA[(j0 + 2) ^ b0] = rA0.z; dA[(j0 + 3) ^ b0] = rA0.w;
            dA[(j1 + 0) ^ b0] = rA1.x; dA[(j1 + 1) ^ b0] = rA1.y;
            dA[(j1 + 2) ^ b0] = rA1.z; dA[(j1 + 3) ^ b0] = rA1.w;
            rA0 = sB[lane]; rA1 = sB[32 + lane];
        }

        // gather oo = 16..31 (covers LDG row B latency)
        #pragma unroll
        for (int g = 4; g < 8; ++g) {
            uint4 qv = jql[g];
            unsigned u[4] = {qv.x, qv.y, qv.z, qv.w};
            #pragma unroll
            for (int i = 0; i < 4; ++i) {
                unsigned w = (half ? (u[i] >> 16) : (u[i] & 0xFFFFu)) ^ lx;
                acc[4 * g + i] += Sb[w & 255u];
                acc[4 * g + i] += Sb[8192 + (w >> 8)];
            }
        }

        if (more) {
            float* dB = drow1base + ((c + 1) & 1) * BUF_F;
            int j0 = lane * 4, j1 = (32 + lane) * 4;
            dB[(j0 + 0) ^ b1] = rA0.x; dB[(j0 + 1) ^ b1] = rA0.y;
            dB[(j0 + 2) ^ b1] = rA0.z; dB[(j0 + 3) ^ b1] = rA0.w;
            dB[(j1 + 0) ^ b1] = rA1.x; dB[(j1 + 1) ^ b1] = rA1.y;
            dB[(j1 + 2) ^ b1] = rA1.z; dB[(j1 + 3) ^ b1] = rA1.w;
        }
        __syncthreads();
    }

    // partial store: g_part[seg][obase+oo][btile*32+lane], coalesced over lane
    float* dst = &g_part[seg][obase][btile * BT + lane];
    #pragma unroll
    for (int oo = 0; oo < 32; ++oo)
        dst[oo * BATCH] = acc[oo];
}

// ---------------- epilogue: seg-split transpose-reduce, high occupancy ----------------
// 1024 blocks x 256 threads; tile = 16 o x 32 b; thread: 1 o x 4 b (float4) x 4 segs;
// two seg-halves combined through smem.
__global__ __launch_bounds__(256) void reduce_kernel(float* __restrict__ out) {
    __shared__ float st[2][16][36];    // [half][o][b], pitch 36
    const int o0 = blockIdx.x * 16;
    const int b0 = blockIdx.y * 32;
    const int t  = threadIdx.x;
    const int h  = t >> 7;             // seg half
    const int r  = t & 127;
    const int oi = r >> 3;             // 0..15
    const int bq = r & 7;              // 0..7 -> b offset 4*bq

    float4 a = make_float4(0.f, 0.f, 0.f, 0.f);
    #pragma unroll
    for (int s = 0; s < 4; ++s) {      // 4 independent coalesced float4 loads
        float4 v = *(const float4*)&g_part[4 * h + s][o0 + oi][b0 + 4 * bq];
        a.x += v.x; a.y += v.y; a.z += v.z; a.w += v.w;
    }
    *(float4*)&st[h][oi][4 * bq] = a;
    __syncthreads();

    const int o  = t & 15;
    const int b2 = t >> 4;             // 0..15
    out[(b0 + b2) * OUTF + o0 + o]      = st[0][o][b2]      + st[1][o][b2];
    out[(b0 + b2 + 16) * OUTF + o0 + o] = st[0][o][b2 + 16] + st[1][o][b2 + 16];
}

// ---------------- launch ----------------
extern "C" void kernel_launch(void* const* d_in, const int* in_sizes, int n_in,
                              void* d_out, int out_size) {
    const int*   inp = (const int*)d_in[0];    // input_indices  [512,32,4]
    const int*   wgt = (const int*)d_in[1];    // weight_indices [1024,32,4]
    const float* lut = (const float*)d_in[2];  // lut_table [256,256]
    float* out = (float*)d_out;

    const int smem_bytes = (JT_U32 + 2 * BUF_F) * 4;   // 16 KB + 128 KB
    cudaFuncSetAttribute(lut_main, cudaFuncAttributeMaxDynamicSharedMemorySize, smem_bytes);
    dim3 grid(BATCH / BT, NSEG);
    lut_main<<<grid, MTHREADS, smem_bytes>>>(inp, wgt, lut);

    reduce_kernel<<<dim3(OUTF / 16, BATCH / 32), 256>>>(out);
}

// round 14
// speedup vs baseline: 1.7912x; 1.7912x over previous
#include <cuda_runtime.h>
#include <cstdint>

// Problem constants
#define BATCH   512
#define OUTF    1024
#define KDIM    128      // NUM_BLOCKS * LATTICE_DIM
#define NIDX    256      // MAX_INDICES

// Tiling for main kernel
#define NSEG    8        // k-segments (grid.y)
#define KSEG    16       // k per segment
#define KCH     2        // k per staging chunk (per buffer)
#define NCH     (KSEG / KCH)       // 8 chunks
#define BT      32       // b per CTA
#define MTHREADS 1024    // 32 warps: warp w owns o = w*32 .. w*32+31
#define BUF_F   (KCH * 32 * 256)   // floats per buffer = 16384 (64 KB)
#define BUF_P   (BUF_F / 2)        // float2 pairs per buffer

// Per-segment partials, [seg][o][b] (b contiguous): 16 MB
__device__ float g_part[NSEG][OUTF][BATCH];

// ---------------- main kernel: double-buffered conflict-free smem gather ----------------
// CTA (btile, seg): b in [btile*32,+32), k in [seg*16,+16), all 1024 o.
// smem: S[buf][kk][b][ j ^ b ]; gather with lane==b is bank-conflict-free.
// Staging: LDG.128 row loads + STS.64 pair stores (b0 even -> (j,j+1) stay adjacent
// under ^b0; odd b1 = same slot, components swapped). Pair slots per 16-lane phase
// are a permutation -> conflict-free.
__global__ __launch_bounds__(MTHREADS, 1) void lut_main(
    const int*   __restrict__ inp,   // [BATCH, KDIM] int32
    const int*   __restrict__ wgt,   // [OUTF, KDIM]  int32
    const float* __restrict__ lut)   // [256, 256]
{
    extern __shared__ float S[];     // 2 * BUF_F floats = 128 KB

    const int btile = blockIdx.x;    // 0..15
    const int seg   = blockIdx.y;    // 0..7
    const int tid   = threadIdx.x;
    const int wid   = tid >> 5;
    const int lane  = tid & 31;
    const int obase = wid * 32;

    // ---- fused pack: this lane's 16 weight indices (o = obase+lane) as 4 byte-words ----
    const int* wp = wgt + (obase + lane) * KDIM + seg * KSEG;
    unsigned jw0, jw1, jw2, jw3;
    {
        int4 v0 = ((const int4*)wp)[0];
        int4 v1 = ((const int4*)wp)[1];
        int4 v2 = ((const int4*)wp)[2];
        int4 v3 = ((const int4*)wp)[3];
        #define CLP(x) ((unsigned)min(max((x), 0), NIDX - 1))
        jw0 = CLP(v0.x) | (CLP(v0.y) << 8) | (CLP(v0.z) << 16) | (CLP(v0.w) << 24);
        jw1 = CLP(v1.x) | (CLP(v1.y) << 8) | (CLP(v1.z) << 16) | (CLP(v1.w) << 24);
        jw2 = CLP(v2.x) | (CLP(v2.y) << 8) | (CLP(v2.z) << 16) | (CLP(v2.w) << 24);
        jw3 = CLP(v3.x) | (CLP(v3.y) << 8) | (CLP(v3.z) << 16) | (CLP(v3.w) << 24);
        #undef CLP
    }
    const unsigned lx = lane * 0x0101u;   // xor folded into bytes 0,1

    // ---- staging assignment: warp stages 2 rows (kk fixed, b0 and b0+1) per chunk ----
    const int kw = wid >> 4;              // kk within chunk: 0 or 1
    const int b0 = (wid & 15) * 2;        // even
    const int b1 = b0 + 1;
    const int* ip0 = inp + (btile * BT + b0) * KDIM + seg * KSEG + kw;
    const int* ip1 = inp + (btile * BT + b1) * KDIM + seg * KSEG + kw;
    float2* drow0p = (float2*)(S + (kw * 32 + b0) * 256);   // + buf*BUF_P at use
    float2* drow1p = (float2*)(S + (kw * 32 + b1) * 256);

    // pair slots (same for both rows; computed with b0)
    const int j0 = 4 * lane, j1 = 128 + 4 * lane;
    const int sl0 = ((j0    ) ^ b0) >> 1;
    const int sl1 = ((j0 + 2) ^ b0) >> 1;
    const int sl2 = ((j1    ) ^ b0) >> 1;
    const int sl3 = ((j1 + 2) ^ b0) >> 1;

    float acc[32];
    #pragma unroll
    for (int i = 0; i < 32; ++i) acc[i] = 0.f;

    // ---- prologue: stage chunk 0 into buffer 0 ----
    {
        int r0 = min(max(ip0[0], 0), NIDX - 1);
        int r1 = min(max(ip1[0], 0), NIDX - 1);
        const float4* s0 = (const float4*)(lut + r0 * 256);
        const float4* s1 = (const float4*)(lut + r1 * 256);
        float4 a0 = s0[lane], a1 = s0[32 + lane];
        float4 c0 = s1[lane], c1 = s1[32 + lane];
        drow0p[sl0] = make_float2(a0.x, a0.y);
        drow0p[sl1] = make_float2(a0.z, a0.w);
        drow0p[sl2] = make_float2(a1.x, a1.y);
        drow0p[sl3] = make_float2(a1.z, a1.w);
        drow1p[sl0] = make_float2(c0.y, c0.x);   // odd b: swapped pair
        drow1p[sl1] = make_float2(c0.w, c0.z);
        drow1p[sl2] = make_float2(c1.y, c1.x);
        drow1p[sl3] = make_float2(c1.w, c1.z);
    }
    __syncthreads();

    // ---- pipelined chunks (split staging: 8 staging floats reused for rows A and B) ----
    #pragma unroll 1
    for (int c = 0; c < NCH; ++c) {
        const bool more = (c < NCH - 1);
        const float4* sA = (const float4*)lut;
        const float4* sB = (const float4*)lut;
        if (more) {
            int r0 = min(max(ip0[(c + 1) * KCH], 0), NIDX - 1);
            int r1 = min(max(ip1[(c + 1) * KCH], 0), NIDX - 1);
            sA = (const float4*)(lut + r0 * 256);
            sB = (const float4*)(lut + r1 * 256);
        }

        const float* Sb = S + (c & 1) * BUF_F + lane * 256;
        unsigned word = (c < 2) ? jw0 : (c < 4) ? jw1 : (c < 6) ? jw2 : jw3;
        unsigned wv = word >> (16 * (c & 1));   // bytes 0,1 = the 2 kk's of chunk c

        float4 r0v, r1v;
        if (more) { r0v = sA[lane]; r1v = sA[32 + lane]; }   // LDG.128 row A

        // gather oo = 0..15
        #pragma unroll
        for (int oo = 0; oo < 16; ++oo) {
            unsigned w = __shfl_sync(0xffffffffu, wv, oo) ^ lx;
            acc[oo] += Sb[w & 255u];
            acc[oo] += Sb[8192 + ((w >> 8) & 255u)];
        }

        if (more) {
            // STS.64 row A, then LDG.128 row B into the same registers
            float2* dA0 = drow0p + ((c + 1) & 1) * BUF_P;
            dA0[sl0] = make_float2(r0v.x, r0v.y);
            dA0[sl1] = make_float2(r0v.z, r0v.w);
            dA0[sl2] = make_float2(r1v.x, r1v.y);
            dA0[sl3] = make_float2(r1v.z, r1v.w);
            r0v = sB[lane]; r1v = sB[32 + lane];
        }

        // gather oo = 16..31 (covers LDG row B latency)
        #pragma unroll
        for (int oo = 16; oo < 32; ++oo) {
            unsigned w = __shfl_sync(0xffffffffu, wv, oo) ^ lx;
            acc[oo] += Sb[w & 255u];
            acc[oo] += Sb[8192 + ((w >> 8) & 255u)];
        }

        if (more) {
            float2* dB1 = drow1p + ((c + 1) & 1) * BUF_P;
            dB1[sl0] = make_float2(r0v.y, r0v.x);   // odd b: swapped pairs
            dB1[sl1] = make_float2(r0v.w, r0v.z);
            dB1[sl2] = make_float2(r1v.y, r1v.x);
            dB1[sl3] = make_float2(r1v.w, r1v.z);
        }
        __syncthreads();
    }

    // partial store: g_part[seg][obase+oo][btile*32+lane], coalesced over lane
    float* dst = &g_part[seg][obase][btile * BT + lane];
    #pragma unroll
    for (int oo = 0; oo < 32; ++oo)
        dst[oo * BATCH] = acc[oo];
}

// ---------------- epilogue: seg-split transpose-reduce (best measured config) ----------------
// 2048 blocks x 128 threads; tile = 8 o x 32 b; thread: 1 o x 4 b (float4) x 4 segs;
// two seg-halves combined through smem.
__global__ __launch_bounds__(128) void reduce_kernel(float* __restrict__ out) {
    __shared__ float st[2][8][36];     // [half][o][b], pitch 36
    const int o0 = blockIdx.x * 8;
    const int b0 = blockIdx.y * 32;
    const int t  = threadIdx.x;
    const int h  = t >> 6;             // seg half
    const int r  = t & 63;
    const int oi = r >> 3;             // 0..7
    const int bq = r & 7;              // 0..7 -> b offset 4*bq

    float4 a = make_float4(0.f, 0.f, 0.f, 0.f);
    #pragma unroll
    for (int s = 0; s < 4; ++s) {      // 4 independent coalesced float4 loads
        float4 v = *(const float4*)&g_part[4 * h + s][o0 + oi][b0 + 4 * bq];
        a.x += v.x; a.y += v.y; a.z += v.z; a.w += v.w;
    }
    *(float4*)&st[h][oi][4 * bq] = a;
    __syncthreads();

    const int oi2 = t & 7;
    const int bb  = t >> 3;            // 0..15
    out[(b0 + bb) * OUTF + o0 + oi2]      = st[0][oi2][bb]      + st[1][oi2][bb];
    out[(b0 + bb + 16) * OUTF + o0 + oi2] = st[0][oi2][bb + 16] + st[1][oi2][bb + 16];
}

// ---------------- launch ----------------
extern "C" void kernel_launch(void* const* d_in, const int* in_sizes, int n_in,
                              void* d_out, int out_size) {
    const int*   inp = (const int*)d_in[0];    // input_indices  [512,32,4]
    const int*   wgt = (const int*)d_in[1];    // weight_indices [1024,32,4]
    const float* lut = (const float*)d_in[2];  // lut_table [256,256]
    float* out = (float*)d_out;

    const int smem_bytes = 2 * BUF_F * (int)sizeof(float);  // 128 KB
    cudaFuncSetAttribute(lut_main, cudaFuncAttributeMaxDynamicSharedMemorySize, smem_bytes);
    dim3 grid(BATCH / BT, NSEG);
    lut_main<<<grid, MTHREADS, smem_bytes>>>(inp, wgt, lut);

    reduce_kernel<<<dim3(OUTF / 8, BATCH / 32), 128>>>(out);
}

// round 15
// speedup vs baseline: 1.9115x; 1.0671x over previous
#include <cuda_runtime.h>
#include <cstdint>

typedef unsigned long long ull;

// Problem constants
#define BATCH   512
#define OUTF    1024
#define KDIM    128      // NUM_BLOCKS * LATTICE_DIM
#define NIDX    256      // MAX_INDICES

// Tiling for main kernel
#define NSEG    8        // k-segments (grid.y)
#define KSEG    16       // k per segment
#define KCH     2        // k per staging chunk (per buffer)
#define NCH     (KSEG / KCH)       // 8 chunks
#define BT      32       // b per CTA
#define MTHREADS 1024    // 32 warps: warp w owns o = w*32 .. w*32+31
#define BUF_F   (KCH * 32 * 256)   // floats per buffer = 16384 (64 KB)
#define BUF_P   (BUF_F / 2)        // float2 pairs per buffer
#define JT_U64  (32 * 64)          // index table: [warp][chunk(8)][group(8)] u64 = 16 KB

// Per-segment partials, [seg][o][b] (b contiguous): 16 MB
__device__ float g_part[NSEG][OUTF][BATCH];

// ---------------- main kernel: double-buffered conflict-free smem gather ----------------
// CTA (btile, seg): b in [btile*32,+32), k in [seg*16,+16), all 1024 o.
// smem buffers: S[buf][kk][b][ j ^ b ]; gather with lane==b is bank-conflict-free.
// Index distribution: per-warp u64 table read as LDS.64 same-address broadcasts
// (1 wavefront per 8 index bytes) instead of per-o SHFL (1 wf per 2 bytes).
// jt[w][c][g] = { lo32: bytes oo=4g..4g+3 for kk0, hi32: same oo's for kk1 }.
__global__ __launch_bounds__(MTHREADS, 1) void lut_main(
    const int*   __restrict__ inp,   // [BATCH, KDIM] int32
    const int*   __restrict__ wgt,   // [OUTF, KDIM]  int32
    const float* __restrict__ lut)   // [256, 256]
{
    extern __shared__ ull SMEM[];             // 16 KB jt + 128 KB buffers
    ull*   jt  = SMEM;                        // [warp][c][g] u64
    float* S   = (float*)(SMEM + JT_U64);     // 2 * BUF_F floats

    const int btile = blockIdx.x;    // 0..15
    const int seg   = blockIdx.y;    // 0..7
    const int tid   = threadIdx.x;
    const int wid   = tid >> 5;
    const int lane  = tid & 31;
    const int obase = wid * 32;

    // ---- build index table: lane l scatters its 16 clipped bytes (o = obase+l) ----
    {
        const int* wp = wgt + (obase + lane) * KDIM + seg * KSEG;
        char* jt8 = (char*)(jt + wid * 64) + (lane >> 2) * 8 + (lane & 3);
        #pragma unroll
        for (int q = 0; q < 4; ++q) {
            int4 v = ((const int4*)wp)[q];
            int b0v = min(max(v.x, 0), NIDX - 1);
            int b1v = min(max(v.y, 0), NIDX - 1);
            int b2v = min(max(v.z, 0), NIDX - 1);
            int b3v = min(max(v.w, 0), NIDX - 1);
            // k' = 4q+m -> chunk c = k'>>1, kk = k'&1; byte addr = (c*8+g)*8 + kk*4 + (l&3)
            jt8[(2 * q + 0) * 64 + 0] = (char)b0v;   // k'=4q+0: c=2q, kk=0
            jt8[(2 * q + 0) * 64 + 4] = (char)b1v;   // k'=4q+1: c=2q, kk=1
            jt8[(2 * q + 1) * 64 + 0] = (char)b2v;   // k'=4q+2: c=2q+1, kk=0
            jt8[(2 * q + 1) * 64 + 4] = (char)b3v;   // k'=4q+3: c=2q+1, kk=1
        }
    }

    // ---- staging assignment: warp stages 2 rows (kk fixed, b0 and b0+1) per chunk ----
    const int kw = wid >> 4;              // kk within chunk: 0 or 1
    const int b0 = (wid & 15) * 2;        // even
    const int* ip0 = inp + (btile * BT + b0) * KDIM + seg * KSEG + kw;
    float2* drow0p = (float2*)(S + (kw * 32 + b0) * 256);   // + buf*BUF_P at use; row b1 = +128 pairs

    // pair slots (same for both rows; computed with even b0)
    const int j0 = 4 * lane, j1 = 128 + 4 * lane;
    const int sl0 = ((j0    ) ^ b0) >> 1;
    const int sl1 = ((j0 + 2) ^ b0) >> 1;
    const int sl2 = ((j1    ) ^ b0) >> 1;
    const int sl3 = ((j1 + 2) ^ b0) >> 1;

    float acc[32];
    #pragma unroll
    for (int i = 0; i < 32; ++i) acc[i] = 0.f;

    // ---- prologue: stage chunk 0 into buffer 0 ----
    {
        int r0 = min(max(ip0[0], 0), NIDX - 1);
        int r1 = min(max(ip0[KDIM], 0), NIDX - 1);
        const float4* s0 = (const float4*)(lut + r0 * 256);
        const float4* s1 = (const float4*)(lut + r1 * 256);
        float4 a0 = s0[lane], a1 = s0[32 + lane];
        float4 c0 = s1[lane], c1 = s1[32 + lane];
        drow0p[sl0] = make_float2(a0.x, a0.y);
        drow0p[sl1] = make_float2(a0.z, a0.w);
        drow0p[sl2] = make_float2(a1.x, a1.y);
        drow0p[sl3] = make_float2(a1.z, a1.w);
        drow0p[sl0 + 128] = make_float2(c0.y, c0.x);   // odd b: swapped pair
        drow0p[sl1 + 128] = make_float2(c0.w, c0.z);
        drow0p[sl2 + 128] = make_float2(c1.y, c1.x);
        drow0p[sl3 + 128] = make_float2(c1.w, c1.z);
    }
    __syncthreads();   // jt + chunk 0 visible

    // ---- pipelined chunks ----
    #pragma unroll 1
    for (int c = 0; c < NCH; ++c) {
        const bool more = (c < NCH - 1);
        const float4* sA = (const float4*)lut;
        const float4* sB = (const float4*)lut;
        if (more) {
            int r0 = min(max(ip0[(c + 1) * KCH], 0), NIDX - 1);
            int r1 = min(max(ip0[(c + 1) * KCH + KDIM], 0), NIDX - 1);
            sA = (const float4*)(lut + r0 * 256);
            sB = (const float4*)(lut + r1 * 256);
        }

        const float* Sb = S + (c & 1) * BUF_F + lane * 256;
        const ull* jrow = jt + wid * 64 + c * 8;   // 8 broadcast words for this chunk

        float4 r0v, r1v;
        if (more) { r0v = sA[lane]; r1v = sA[32 + lane]; }   // LDG.128 row A

        ull u = jrow[0];                     // LDS.64 broadcast (1 wf)
        // gather oo = 0..15 (groups 0..3), one-group prefetch
        #pragma unroll
        for (int g = 0; g < 4; ++g) {
            ull un = jrow[g + 1];
            unsigned lo = (unsigned)u, hi = (unsigned)(u >> 32);
            #pragma unroll
            for (int i = 0; i < 4; ++i) {
                unsigned a = ((lo >> (8 * i)) & 255u) ^ (unsigned)lane;
                unsigned b = ((hi >> (8 * i)) & 255u) ^ (unsigned)lane;
                acc[4 * g + i] += Sb[a] + Sb[8192 + b];
            }
            u = un;
        }

        if (more) {
            // STS.64 row A, then LDG.128 row B into the same registers
            float2* dA0 = drow0p + ((c + 1) & 1) * BUF_P;
            dA0[sl0] = make_float2(r0v.x, r0v.y);
            dA0[sl1] = make_float2(r0v.z, r0v.w);
            dA0[sl2] = make_float2(r1v.x, r1v.y);
            dA0[sl3] = make_float2(r1v.z, r1v.w);
            r0v = sB[lane]; r1v = sB[32 + lane];
        }

        // gather oo = 16..31 (groups 4..7)
        #pragma unroll
        for (int g = 4; g < 8; ++g) {
            ull un = (g < 7) ? jrow[g + 1] : 0ull;
            unsigned lo = (unsigned)u, hi = (unsigned)(u >> 32);
            #pragma unroll
            for (int i = 0; i < 4; ++i) {
                unsigned a = ((lo >> (8 * i)) & 255u) ^ (unsigned)lane;
                unsigned b = ((hi >> (8 * i)) & 255u) ^ (unsigned)lane;
                acc[4 * g + i] += Sb[a] + Sb[8192 + b];
            }
            u = un;
        }

        if (more) {
            float2* dB1 = drow0p + ((c + 1) & 1) * BUF_P + 128;
            dB1[sl0] = make_float2(r0v.y, r0v.x);   // odd b: swapped pairs
            dB1[sl1] = make_float2(r0v.w, r0v.z);
            dB1[sl2] = make_float2(r1v.y, r1v.x);
            dB1[sl3] = make_float2(r1v.w, r1v.z);
        }
        __syncthreads();
    }

    // partial store: g_part[seg][obase+oo][btile*32+lane], coalesced over lane
    float* dst = &g_part[seg][obase][btile * BT + lane];
    #pragma unroll
    for (int oo = 0; oo < 32; ++oo)
        dst[oo * BATCH] = acc[oo];
}

// ---------------- epilogue: seg-split transpose-reduce (best measured config) ----------------
// 2048 blocks x 128 threads; tile = 8 o x 32 b; thread: 1 o x 4 b (float4) x 4 segs;
// two seg-halves combined through smem.
__global__ __launch_bounds__(128) void reduce_kernel(float* __restrict__ out) {
    __shared__ float st[2][8][36];     // [half][o][b], pitch 36
    const int o0 = blockIdx.x * 8;
    const int b0 = blockIdx.y * 32;
    const int t  = threadIdx.x;
    const int h  = t >> 6;             // seg half
    const int r  = t & 63;
    const int oi = r >> 3;             // 0..7
    const int bq = r & 7;              // 0..7 -> b offset 4*bq

    float4 a = make_float4(0.f, 0.f, 0.f, 0.f);
    #pragma unroll
    for (int s = 0; s < 4; ++s) {      // 4 independent coalesced float4 loads
        float4 v = *(const float4*)&g_part[4 * h + s][o0 + oi][b0 + 4 * bq];
        a.x += v.x; a.y += v.y; a.z += v.z; a.w += v.w;
    }
    *(float4*)&st[h][oi][4 * bq] = a;
    __syncthreads();

    const int oi2 = t & 7;
    const int bb  = t >> 3;            // 0..15
    out[(b0 + bb) * OUTF + o0 + oi2]      = st[0][oi2][bb]      + st[1][oi2][bb];
    out[(b0 + bb + 16) * OUTF + o0 + oi2] = st[0][oi2][bb + 16] + st[1][oi2][bb + 16];
}

// ---------------- launch ----------------
extern "C" void kernel_launch(void* const* d_in, const int* in_sizes, int n_in,
                              void* d_out, int out_size) {
    const int*   inp = (const int*)d_in[0];    // input_indices  [512,32,4]
    const int*   wgt = (const int*)d_in[1];    // weight_indices [1024,32,4]
    const float* lut = (const float*)d_in[2];  // lut_table [256,256]
    float* out = (float*)d_out;

    const int smem_bytes = JT_U64 * 8 + 2 * BUF_F * 4;   // 16 KB + 128 KB
    cudaFuncSetAttribute(lut_main, cudaFuncAttributeMaxDynamicSharedMemorySize, smem_bytes);
    dim3 grid(BATCH / BT, NSEG);
    lut_main<<<grid, MTHREADS, smem_bytes>>>(inp, wgt, lut);

    reduce_kernel<<<dim3(OUTF / 8, BATCH / 32), 128>>>(out);
}